// round 7
// baseline (speedup 1.0000x reference)
#include <cuda_runtime.h>
#include <cuda_fp16.h>
#include <math.h>
#include <stdint.h>

// Problem dims
#define Bsz  256
#define Tsz  256
#define INsz 4
#define HPsz 64
#define Esz  512
#define Hsz  1024
#define Dsz  4
#define ROWS (Bsz * Tsz)   // 65536

// ---------------------------------------------------------------------------
// Scratch (device globals; no allocation allowed)
// ---------------------------------------------------------------------------
__device__ float  g_x  [(size_t)ROWS * Esz];   // residual stream fp32
__device__ __half g_xhi[(size_t)ROWS * Esz];   // fp16 split of x (hi)
__device__ __half g_xlo[(size_t)ROWS * Esz];   // fp16 split of x (lo)
__device__ float  g_h1 [(size_t)ROWS * Hsz];   // GEMM1 out fp32
__device__ __half g_spk[(size_t)ROWS * Hsz];   // spikes fp16 (exact 0/1)
__device__ float  g_h2 [(size_t)ROWS * Esz];   // GEMM2 out fp32
__device__ float  g_mean[ROWS];                // LN row mean
__device__ float  g_rstd[ROWS];                // LN row inv-std
// transposed fp16 weight splits: Wt1 [D][H][E], Wt2 [D][E][H]
__device__ __half g_w1hi[(size_t)Dsz * Hsz * Esz];
__device__ __half g_w1lo[(size_t)Dsz * Hsz * Esz];
__device__ __half g_w2hi[(size_t)Dsz * Esz * Hsz];
__device__ __half g_w2lo[(size_t)Dsz * Esz * Hsz];

// ---------------------------------------------------------------------------
// Helpers
// ---------------------------------------------------------------------------
__device__ __forceinline__ uint32_t sw128(uint32_t b) { return b ^ ((b >> 3) & 0x70); }

__device__ __forceinline__ uint32_t s2u(const void* p) {
    uint32_t a;
    asm("{ .reg .u64 t; cvta.to.shared.u64 t, %1; cvt.u32.u64 %0, t; }" : "=r"(a) : "l"(p));
    return a;
}

__device__ __forceinline__ void cp16(uint32_t saddr, const void* g) {
    asm volatile("cp.async.cg.shared.global [%0], [%1], 16;" :: "r"(saddr), "l"(g));
}

#define LDSM4(r0, r1, r2, r3, addr)                                           \
    asm volatile("ldmatrix.sync.aligned.m8n8.x4.shared.b16 {%0,%1,%2,%3}, [%4];" \
                 : "=r"(r0), "=r"(r1), "=r"(r2), "=r"(r3) : "r"(addr))

#define MMA16816(d, a, b)                                                     \
    asm volatile(                                                             \
        "mma.sync.aligned.m16n8k16.row.col.f32.f16.f16.f32 "                  \
        "{%0,%1,%2,%3},{%4,%5,%6,%7},{%8,%9},{%0,%1,%2,%3};"                  \
        : "+f"((d)[0]), "+f"((d)[1]), "+f"((d)[2]), "+f"((d)[3])              \
        : "r"((a)[0]), "r"((a)[1]), "r"((a)[2]), "r"((a)[3]),                 \
          "r"((b)[0]), "r"((b)[1]))

// ---------------------------------------------------------------------------
// Split+transpose weights: src [L][K][N] fp32 -> dst [L][N][K] fp16 hi/lo
// ---------------------------------------------------------------------------
__global__ void split_w(const float* __restrict__ W, __half* __restrict__ hi,
                        __half* __restrict__ lo, int K, int N) {
    int idx = blockIdx.x * blockDim.x + threadIdx.x;
    if (idx >= K * N) return;
    size_t lofs = (size_t)blockIdx.y * K * N;
    int k = idx / N, n = idx % N;
    float w = W[lofs + idx];
    __half h = __float2half_rn(w);
    hi[lofs + (size_t)n * K + k] = h;
    lo[lofs + (size_t)n * K + k] = __float2half_rn(w - __half2float(h));
}

// ---------------------------------------------------------------------------
// GEMM: C[M, Ntot] = Ahi@Bhi^T + Ahi@Blo^T (+ Alo@Bhi^T) + bias
// mma.sync m16n8k16, CTA 128x128, BK=64, 8 warps (4x2), 3-stage cp.async,
// TILES consecutive N-tiles per CTA with a continuous pipeline.
// ---------------------------------------------------------------------------
template <int TERMS> struct Geo {
    static constexpr int OFF_ALO = 16384;
    static constexpr int OFF_BHI = (TERMS == 3) ? 32768 : 16384;
    static constexpr int OFF_BLO = OFF_BHI + 16384;
    static constexpr int STG     = OFF_BLO + 16384;   // 64KB / 48KB
    static constexpr int TOT     = 3 * STG;
};

template <int TERMS, int KK>
__device__ __forceinline__ void load_stage(uint32_t sbase,
                                           const __half* A, const __half* Al,
                                           const __half* B, const __half* Bl,
                                           int k0, int tid) {
#pragma unroll
    for (int it = 0; it < 4; it++) {
        int idx = tid + it * 256;
        int r = idx >> 3, c = idx & 7;
        uint32_t so = sw128((uint32_t)(r * 128 + c * 16));
        size_t go = (size_t)r * KK + k0 + c * 8;
        cp16(sbase + so, A + go);
        if (TERMS == 3) cp16(sbase + Geo<TERMS>::OFF_ALO + so, Al + go);
        cp16(sbase + Geo<TERMS>::OFF_BHI + so, B + go);
        cp16(sbase + Geo<TERMS>::OFF_BLO + so, Bl + go);
    }
    asm volatile("cp.async.commit_group;" ::: "memory");
}

template <int TERMS>
__device__ __forceinline__ void load_frags(uint32_t stg, int ks,
                                           int warp_m, int warp_n, int lane,
                                           uint32_t (&ahi)[2][4], uint32_t (&alo)[2][4],
                                           uint32_t (&bhi)[8][2], uint32_t (&blo)[8][2]) {
    int row_in = lane & 7, grp = lane >> 3;
#pragma unroll
    for (int mf = 0; mf < 2; mf++) {
        int r = warp_m * 32 + mf * 16 + (grp & 1) * 8 + row_in;
        int kb = ks * 32 + (grp >> 1) * 16;
        uint32_t off = sw128((uint32_t)(r * 128 + kb));
        LDSM4(ahi[mf][0], ahi[mf][1], ahi[mf][2], ahi[mf][3], stg + off);
        if (TERMS == 3)
            LDSM4(alo[mf][0], alo[mf][1], alo[mf][2], alo[mf][3],
                  stg + Geo<TERMS>::OFF_ALO + off);
    }
#pragma unroll
    for (int p = 0; p < 4; p++) {
        int r = warp_n * 64 + p * 16 + (grp >> 1) * 8 + row_in;
        int kb = ks * 32 + (grp & 1) * 16;
        uint32_t off = sw128((uint32_t)(r * 128 + kb));
        uint32_t t0, t1, t2, t3;
        LDSM4(t0, t1, t2, t3, stg + Geo<TERMS>::OFF_BHI + off);
        bhi[2 * p][0] = t0; bhi[2 * p][1] = t1;
        bhi[2 * p + 1][0] = t2; bhi[2 * p + 1][1] = t3;
        LDSM4(t0, t1, t2, t3, stg + Geo<TERMS>::OFF_BLO + off);
        blo[2 * p][0] = t0; blo[2 * p][1] = t1;
        blo[2 * p + 1][0] = t2; blo[2 * p + 1][1] = t3;
    }
}

template <int TERMS, int TILES, int KK, int NTOT>
__global__ void __launch_bounds__(256, 1)
gemm_hs(const __half* __restrict__ Ahi, const __half* __restrict__ Alo,
        const __half* __restrict__ Bhi, const __half* __restrict__ Blo,
        const float* __restrict__ bias, float* __restrict__ C) {
    extern __shared__ char smc[];
    uint32_t sb = s2u(smc);
    int tid = threadIdx.x;
    int wid = tid >> 5, lane = tid & 31;
    int warp_m = wid >> 1, warp_n = wid & 1;
    int bxg = blockIdx.x, by = blockIdx.y;

    constexpr int NC = KK / 64;
    constexpr int TC = TILES * NC;

    const __half* Ah = Ahi + (size_t)(by * 128) * KK;
    const __half* Al = Alo + (size_t)(by * 128) * KK;

    float acc[2][8][4] = {};
    uint32_t ahi[2][2][4], alo[2][2][4], bhi[2][8][2], blo[2][8][2];

    {
        const __half* Bh0 = Bhi + (size_t)(bxg * TILES * 128) * KK;
        const __half* Bl0 = Blo + (size_t)(bxg * TILES * 128) * KK;
        load_stage<TERMS, KK>(sb + 0 * Geo<TERMS>::STG, Ah, Al, Bh0, Bl0, 0, tid);
        load_stage<TERMS, KK>(sb + 1 * Geo<TERMS>::STG, Ah, Al, Bh0, Bl0, 64, tid);
    }

    for (int tile = 0; tile < TILES; tile++) {
        for (int c = 0; c < NC; c++) {
            int g = tile * NC + c;
            if (g + 1 < TC)
                asm volatile("cp.async.wait_group 1;" ::: "memory");
            else
                asm volatile("cp.async.wait_group 0;" ::: "memory");
            __syncthreads();

            int g2 = g + 2;
            if (g2 < TC) {
                int t2 = g2 / NC, c2 = g2 % NC;
                const __half* Bh2 = Bhi + (size_t)((bxg * TILES + t2) * 128) * KK;
                const __half* Bl2 = Blo + (size_t)((bxg * TILES + t2) * 128) * KK;
                load_stage<TERMS, KK>(sb + (g2 % 3) * Geo<TERMS>::STG,
                                      Ah, Al, Bh2, Bl2, c2 * 64, tid);
            }

            uint32_t stg = sb + (g % 3) * Geo<TERMS>::STG;
            load_frags<TERMS>(stg, 0, warp_m, warp_n, lane, ahi[0], alo[0], bhi[0], blo[0]);
#pragma unroll
            for (int ks = 0; ks < 4; ks++) {
                int cur = ks & 1, nxt = cur ^ 1;
                if (ks < 3)
                    load_frags<TERMS>(stg, ks + 1, warp_m, warp_n, lane,
                                      ahi[nxt], alo[nxt], bhi[nxt], blo[nxt]);
#pragma unroll
                for (int mf = 0; mf < 2; mf++)
#pragma unroll
                    for (int nf = 0; nf < 8; nf++)
                        MMA16816(acc[mf][nf], ahi[cur][mf], bhi[cur][nf]);
#pragma unroll
                for (int mf = 0; mf < 2; mf++)
#pragma unroll
                    for (int nf = 0; nf < 8; nf++)
                        MMA16816(acc[mf][nf], ahi[cur][mf], blo[cur][nf]);
                if (TERMS == 3) {
#pragma unroll
                    for (int mf = 0; mf < 2; mf++)
#pragma unroll
                        for (int nf = 0; nf < 8; nf++)
                            MMA16816(acc[mf][nf], alo[cur][mf], bhi[cur][nf]);
                }
            }
        }

        {
            int col_base = (bxg * TILES + tile) * 128 + warp_n * 64 + (lane & 3) * 2;
            int row_base = by * 128 + warp_m * 32 + (lane >> 2);
#pragma unroll
            for (int mf = 0; mf < 2; mf++)
#pragma unroll
                for (int nf = 0; nf < 8; nf++) {
                    int col = col_base + nf * 8;
                    float b0 = __ldg(bias + col), b1 = __ldg(bias + col + 1);
                    int r0 = row_base + mf * 16;
                    float2 v0 = { acc[mf][nf][0] + b0, acc[mf][nf][1] + b1 };
                    float2 v1 = { acc[mf][nf][2] + b0, acc[mf][nf][3] + b1 };
                    *(float2*)(C + (size_t)r0 * NTOT + col) = v0;
                    *(float2*)(C + (size_t)(r0 + 8) * NTOT + col) = v1;
                }
#pragma unroll
            for (int mf = 0; mf < 2; mf++)
#pragma unroll
                for (int nf = 0; nf < 8; nf++)
#pragma unroll
                    for (int q = 0; q < 4; q++) acc[mf][nf][q] = 0.0f;
        }
    }
}

// ---------------------------------------------------------------------------
// Input projector, tiled: 16 rows per block, W2 read once per block.
// hpT stored transposed [k][r] so the k-loop reads float4 broadcasts.
// Per-output FMA order identical to the original (init b2, k ascending).
// ---------------------------------------------------------------------------
#define PR 16   // rows per block
__global__ void __launch_bounds__(256)
proj_kernel(const float* __restrict__ hist,
            const float* __restrict__ W1, const float* __restrict__ b1,
            const float* __restrict__ W2, const float* __restrict__ b2,
            float* __restrict__ out,
            __half* __restrict__ ohi, __half* __restrict__ olo) {
    __shared__ float hs[PR * INsz];        // 16 rows x 4 inputs
    __shared__ float hpT[HPsz][PR];        // transposed hidden [64][16]
    int rb = blockIdx.x * PR;
    int tid = threadIdx.x;

    if (tid < PR * INsz) hs[tid] = hist[(size_t)rb * INsz + tid];
    __syncthreads();

#pragma unroll
    for (int i = 0; i < (PR * HPsz) / 256; i++) {   // 4 iters
        int idx = tid + i * 256;
        int r = idx >> 6, cc = idx & 63;
        float a = b1[cc];
#pragma unroll
        for (int k = 0; k < INsz; k++) a += hs[r * INsz + k] * W1[k * HPsz + cc];
        hpT[cc][r] = 0.5f * a * (1.0f + erff(a * 0.70710678118654752440f));
    }
    __syncthreads();

    int c0 = tid * 2;   // each thread owns 2 consecutive columns
    float acc[PR][2];
    float bb0 = b2[c0], bb1 = b2[c0 + 1];
#pragma unroll
    for (int r = 0; r < PR; r++) { acc[r][0] = bb0; acc[r][1] = bb1; }

    for (int k = 0; k < HPsz; k++) {
        float2 w = *(const float2*)(W2 + (size_t)k * Esz + c0);
        float4 h0 = *(const float4*)&hpT[k][0];
        float4 h1 = *(const float4*)&hpT[k][4];
        float4 h2 = *(const float4*)&hpT[k][8];
        float4 h3 = *(const float4*)&hpT[k][12];
        float hk[PR] = { h0.x, h0.y, h0.z, h0.w, h1.x, h1.y, h1.z, h1.w,
                         h2.x, h2.y, h2.z, h2.w, h3.x, h3.y, h3.z, h3.w };
#pragma unroll
        for (int r = 0; r < PR; r++) {
            acc[r][0] += hk[r] * w.x;
            acc[r][1] += hk[r] * w.y;
        }
    }

#pragma unroll
    for (int r = 0; r < PR; r++) {
        size_t off = (size_t)(rb + r) * Esz + c0;
        float a0 = acc[r][0], a1 = acc[r][1];
        *(float2*)(out + off) = make_float2(a0, a1);
        __half h0 = __float2half_rn(a0), h1 = __float2half_rn(a1);
        *(__half2*)(ohi + off) = __halves2half2(h0, h1);
        *(__half2*)(olo + off) = __halves2half2(
            __float2half_rn(a0 - __half2float(h0)),
            __float2half_rn(a1 - __half2float(h1)));
    }
}

// ---------------------------------------------------------------------------
// Block reduce (order-exact match to prior rounds)
// ---------------------------------------------------------------------------
__device__ __forceinline__ float block_reduce_sum(float v) {
    __shared__ float smr[32];
    int lane = threadIdx.x & 31, wid = threadIdx.x >> 5;
#pragma unroll
    for (int o = 16; o > 0; o >>= 1) v += __shfl_xor_sync(0xffffffffu, v, o);
    __syncthreads();
    if (lane == 0) smr[wid] = v;
    __syncthreads();
    if (wid == 0) {
        v = (lane < (int)(blockDim.x >> 5)) ? smr[lane] : 0.0f;
#pragma unroll
        for (int o = 16; o > 0; o >>= 1) v += __shfl_xor_sync(0xffffffffu, v, o);
        if (lane == 0) smr[0] = v;
    }
    __syncthreads();
    return smr[0];
}

// ---------------------------------------------------------------------------
// LN stats: one block per row, bit-identical reduction tree. Writes (mean, rstd).
// ---------------------------------------------------------------------------
template <int N, int NTHR>
__global__ void ln_stats(const float* __restrict__ x,
                         float* __restrict__ mean, float* __restrict__ rstd) {
    size_t row = blockIdx.x;
    const float4* p = (const float4*)(x + row * (size_t)N);
    int tid = threadIdx.x;

    float4 v = p[tid];
    float s = v.x + v.y + v.z + v.w;
    float m = block_reduce_sum(s) * (1.0f / N);

    float dx = v.x - m, dy = v.y - m, dz = v.z - m, dw = v.w - m;
    float var = block_reduce_sum(dx * dx + dy * dy + dz * dz + dw * dw) * (1.0f / N);
    float inv = 1.0f / sqrtf(var + 1e-5f);

    if (tid == 0) { mean[row] = m; rstd[row] = inv; }
}

// ---------------------------------------------------------------------------
// LIF apply (spike emit), float4 per thread (4 channels), normalize on the fly.
// ---------------------------------------------------------------------------
__global__ void lif_apply(const float4* __restrict__ h4,
                          const float* __restrict__ mean, const float* __restrict__ rstd,
                          const float4* __restrict__ gamma4, const float4* __restrict__ beta4,
                          uint2* __restrict__ spk4, int C4) {
    int idx = blockIdx.x * blockDim.x + threadIdx.x;
    if (idx >= Bsz * C4) return;
    int b = idx / C4, j = idx % C4;
    float4 gg = gamma4[j], bb = beta4[j];
    float v0 = 0.f, v1 = 0.f, v2 = 0.f, v3 = 0.f;
    size_t base = (size_t)b * Tsz * C4 + j;
    int rbase = b * Tsz;
#pragma unroll 4
    for (int t = 0; t < Tsz; t++) {
        float4 xi = h4[base + (size_t)t * C4];
        float m = __ldg(mean + rbase + t);
        float inv = __ldg(rstd + rbase + t);
        float n0 = (xi.x - m) * inv * gg.x + bb.x;
        float n1 = (xi.y - m) * inv * gg.y + bb.y;
        float n2 = (xi.z - m) * inv * gg.z + bb.z;
        float n3 = (xi.w - m) * inv * gg.w + bb.w;
        v0 = v0 + (n0 - v0) * 0.5f;
        v1 = v1 + (n1 - v1) * 0.5f;
        v2 = v2 + (n2 - v2) * 0.5f;
        v3 = v3 + (n3 - v3) * 0.5f;
        float s0 = 0.f, s1 = 0.f, s2 = 0.f, s3 = 0.f;
        if (v0 >= 1.0f) { s0 = 1.0f; v0 = 0.f; }
        if (v1 >= 1.0f) { s1 = 1.0f; v1 = 0.f; }
        if (v2 >= 1.0f) { s2 = 1.0f; v2 = 0.f; }
        if (v3 >= 1.0f) { s3 = 1.0f; v3 = 0.f; }
        __half2 lo2 = __halves2half2(__float2half_rn(s0), __float2half_rn(s1));
        __half2 hi2 = __halves2half2(__float2half_rn(s2), __float2half_rn(s3));
        uint2 pack = { *(uint32_t*)&lo2, *(uint32_t*)&hi2 };
        spk4[base + (size_t)t * C4] = pack;
    }
}

// LIF apply + residual add + sparse split refresh (float4 reads, sparse writes)
__global__ void lifadd_apply(const float4* __restrict__ h4,
                             const float* __restrict__ mean, const float* __restrict__ rstd,
                             const float4* __restrict__ gamma4, const float4* __restrict__ beta4,
                             float* __restrict__ x, __half* __restrict__ xhi,
                             __half* __restrict__ xlo, int C4) {
    int idx = blockIdx.x * blockDim.x + threadIdx.x;
    if (idx >= Bsz * C4) return;
    int b = idx / C4, j = idx % C4;
    float4 gg = gamma4[j], bb = beta4[j];
    float v0 = 0.f, v1 = 0.f, v2 = 0.f, v3 = 0.f;
    size_t base = (size_t)b * Tsz * C4 + j;
    int rbase = b * Tsz;
    int C = C4 * 4;
#pragma unroll 4
    for (int t = 0; t < Tsz; t++) {
        float4 xi = h4[base + (size_t)t * C4];
        float m = __ldg(mean + rbase + t);
        float inv = __ldg(rstd + rbase + t);
        float n0 = (xi.x - m) * inv * gg.x + bb.x;
        float n1 = (xi.y - m) * inv * gg.y + bb.y;
        float n2 = (xi.z - m) * inv * gg.z + bb.z;
        float n3 = (xi.w - m) * inv * gg.w + bb.w;
        v0 = v0 + (n0 - v0) * 0.5f;
        v1 = v1 + (n1 - v1) * 0.5f;
        v2 = v2 + (n2 - v2) * 0.5f;
        v3 = v3 + (n3 - v3) * 0.5f;
        size_t o = (size_t)b * Tsz * C + (size_t)t * C + j * 4;
#pragma unroll
        for (int cc = 0; cc < 4; cc++) {
            float* vp = (cc == 0) ? &v0 : (cc == 1) ? &v1 : (cc == 2) ? &v2 : &v3;
            if (*vp >= 1.0f) {
                *vp = 0.f;
                float xv = x[o + cc] + 1.0f;
                x[o + cc] = xv;
                __half hh = __float2half_rn(xv);
                xhi[o + cc] = hh;
                xlo[o + cc] = __float2half_rn(xv - __half2float(hh));
            }
        }
    }
}

// Extract last timestep
__global__ void last_kernel(const float* __restrict__ x, float* __restrict__ out) {
    int i = blockIdx.x * blockDim.x + threadIdx.x;
    if (i < Bsz * Esz) {
        int b = i / Esz, e = i % Esz;
        out[i] = x[((size_t)b * Tsz + (Tsz - 1)) * Esz + e];
    }
}

// ---------------------------------------------------------------------------
extern "C" void kernel_launch(void* const* d_in, const int* in_sizes, int n_in,
                              void* d_out, int out_size) {
    const float* hist  = (const float*)d_in[0];
    const float* pW1   = (const float*)d_in[1];
    const float* pb1   = (const float*)d_in[2];
    const float* pW2   = (const float*)d_in[3];
    const float* pb2   = (const float*)d_in[4];
    const float* fc1_w = (const float*)d_in[5];
    const float* fc1_b = (const float*)d_in[6];
    const float* ln1_g = (const float*)d_in[7];
    const float* ln1_b = (const float*)d_in[8];
    const float* fc2_w = (const float*)d_in[9];
    const float* fc2_b = (const float*)d_in[10];
    const float* ln2_g = (const float*)d_in[11];
    const float* ln2_b = (const float*)d_in[12];

    float *x, *h1, *h2, *mean, *rstd;
    __half *xhi, *xlo, *spk, *w1hi, *w1lo, *w2hi, *w2lo;
    cudaGetSymbolAddress((void**)&x,    g_x);
    cudaGetSymbolAddress((void**)&h1,   g_h1);
    cudaGetSymbolAddress((void**)&h2,   g_h2);
    cudaGetSymbolAddress((void**)&mean, g_mean);
    cudaGetSymbolAddress((void**)&rstd, g_rstd);
    cudaGetSymbolAddress((void**)&xhi,  g_xhi);
    cudaGetSymbolAddress((void**)&xlo,  g_xlo);
    cudaGetSymbolAddress((void**)&spk,  g_spk);
    cudaGetSymbolAddress((void**)&w1hi, g_w1hi);
    cudaGetSymbolAddress((void**)&w1lo, g_w1lo);
    cudaGetSymbolAddress((void**)&w2hi, g_w2hi);
    cudaGetSymbolAddress((void**)&w2lo, g_w2lo);

    auto* gk1 = gemm_hs<3, 4, Esz, Hsz>;   // GEMM1: K=512, N=1024, 4 tiles/CTA
    auto* gk2 = gemm_hs<2, 2, Hsz, Esz>;   // GEMM2: K=1024, N=512, 2 tiles/CTA
    cudaFuncSetAttribute(gk1, cudaFuncAttributeMaxDynamicSharedMemorySize, Geo<3>::TOT);
    cudaFuncSetAttribute(gk2, cudaFuncAttributeMaxDynamicSharedMemorySize, Geo<2>::TOT);

    split_w<<<dim3((Esz * Hsz + 255) / 256, Dsz), 256>>>(fc1_w, w1hi, w1lo, Esz, Hsz);
    split_w<<<dim3((Hsz * Esz + 255) / 256, Dsz), 256>>>(fc2_w, w2hi, w2lo, Hsz, Esz);

    proj_kernel<<<ROWS / PR, 256>>>(hist, pW1, pb1, pW2, pb2, x, xhi, xlo);

    for (int d = 0; d < Dsz; d++) {
        size_t o1 = (size_t)d * Hsz * Esz;   // Wt1 [H][E] per layer
        size_t o2 = (size_t)d * Esz * Hsz;   // Wt2 [E][H] per layer

        gk1<<<dim3(Hsz / 128 / 4, ROWS / 128), 256, Geo<3>::TOT>>>(
            xhi, xlo, w1hi + o1, w1lo + o1, fc1_b + d * Hsz, h1);
        ln_stats<Hsz, 256><<<ROWS, 256>>>(h1, mean, rstd);
        lif_apply<<<(Bsz * (Hsz / 4) + 255) / 256, 256>>>(
            (const float4*)h1, mean, rstd, (const float4*)(ln1_g + d * Hsz),
            (const float4*)(ln1_b + d * Hsz), (uint2*)spk, Hsz / 4);

        gk2<<<dim3(Esz / 128 / 2, ROWS / 128), 256, Geo<2>::TOT>>>(
            spk, spk, w2hi + o2, w2lo + o2, fc2_b + d * Esz, h2);
        ln_stats<Esz, 128><<<ROWS, 128>>>(h2, mean, rstd);
        lifadd_apply<<<(Bsz * (Esz / 4) + 255) / 256, 256>>>(
            (const float4*)h2, mean, rstd, (const float4*)(ln2_g + d * Esz),
            (const float4*)(ln2_b + d * Esz), x, xhi, xlo, Esz / 4);
    }

    last_kernel<<<(Bsz * Esz + 255) / 256, 256>>>(x, (float*)d_out);
}

// round 9
// speedup vs baseline: 1.0589x; 1.0589x over previous
#include <cuda_runtime.h>
#include <cuda_fp16.h>
#include <math.h>
#include <stdint.h>

// Problem dims
#define Bsz  256
#define Tsz  256
#define INsz 4
#define HPsz 64
#define Esz  512
#define Hsz  1024
#define Dsz  4
#define ROWS (Bsz * Tsz)   // 65536

// ---------------------------------------------------------------------------
// Scratch (device globals; no allocation allowed)
// ---------------------------------------------------------------------------
__device__ float  g_x  [(size_t)ROWS * Esz];
__device__ __half g_xhi[(size_t)ROWS * Esz];
__device__ __half g_xlo[(size_t)ROWS * Esz];
__device__ float  g_h1 [(size_t)ROWS * Hsz];
__device__ __half g_spk[(size_t)ROWS * Hsz];
__device__ float  g_h2 [(size_t)ROWS * Esz];
__device__ float  g_mean[ROWS];
__device__ float  g_rstd[ROWS];
__device__ __half g_w1hi[(size_t)Dsz * Hsz * Esz];
__device__ __half g_w1lo[(size_t)Dsz * Hsz * Esz];
__device__ __half g_w2hi[(size_t)Dsz * Esz * Hsz];
__device__ __half g_w2lo[(size_t)Dsz * Esz * Hsz];

// ---------------------------------------------------------------------------
// Helpers
// ---------------------------------------------------------------------------
__device__ __forceinline__ uint32_t sw128(uint32_t b) { return b ^ ((b >> 3) & 0x70); }

__device__ __forceinline__ uint32_t s2u(const void* p) {
    uint32_t a;
    asm("{ .reg .u64 t; cvta.to.shared.u64 t, %1; cvt.u32.u64 %0, t; }" : "=r"(a) : "l"(p));
    return a;
}

__device__ __forceinline__ void cp16(uint32_t saddr, const void* g) {
    asm volatile("cp.async.cg.shared.global [%0], [%1], 16;" :: "r"(saddr), "l"(g));
}

#define LDSM4(r0, r1, r2, r3, addr)                                           \
    asm volatile("ldmatrix.sync.aligned.m8n8.x4.shared.b16 {%0,%1,%2,%3}, [%4];" \
                 : "=r"(r0), "=r"(r1), "=r"(r2), "=r"(r3) : "r"(addr))

#define MMA16816(d, a, b)                                                     \
    asm volatile(                                                             \
        "mma.sync.aligned.m16n8k16.row.col.f32.f16.f16.f32 "                  \
        "{%0,%1,%2,%3},{%4,%5,%6,%7},{%8,%9},{%0,%1,%2,%3};"                  \
        : "+f"((d)[0]), "+f"((d)[1]), "+f"((d)[2]), "+f"((d)[3])              \
        : "r"((a)[0]), "r"((a)[1]), "r"((a)[2]), "r"((a)[3]),                 \
          "r"((b)[0]), "r"((b)[1]))

// ---------------------------------------------------------------------------
// Split+transpose weights
// ---------------------------------------------------------------------------
__global__ void split_w(const float* __restrict__ W, __half* __restrict__ hi,
                        __half* __restrict__ lo, int K, int N) {
    int idx = blockIdx.x * blockDim.x + threadIdx.x;
    if (idx >= K * N) return;
    size_t lofs = (size_t)blockIdx.y * K * N;
    int k = idx / N, n = idx % N;
    float w = W[lofs + idx];
    __half h = __float2half_rn(w);
    hi[lofs + (size_t)n * K + k] = h;
    lo[lofs + (size_t)n * K + k] = __float2half_rn(w - __half2float(h));
}

// ---------------------------------------------------------------------------
// GEMM: C[M, NTOT] = Ahi@Bhi^T + Ahi@Blo^T (+ Alo@Bhi^T) + bias
// CTA tile 256x128, warp tile 64x64 (8 warps 4x2), BK=64, 2-stage cp.async.
// A IS reloaded every chunk (round-8 staleness bug fixed).
// ---------------------------------------------------------------------------
template <int TERMS> struct G2 {
    static constexpr int AHI = 0;                                  // 32 KB
    static constexpr int ALO = 32768;                              // 32 KB (TERMS==3)
    static constexpr int BHI = (TERMS == 3) ? 65536 : 32768;       // 16 KB
    static constexpr int BLO = BHI + 16384;                        // 16 KB
    static constexpr int STG = BLO + 16384;                        // 96 KB / 64 KB
    static constexpr int TOT = 2 * STG;                            // 192 KB / 128 KB
};

template <int TERMS, int KK>
__device__ __forceinline__ void load_stage256(uint32_t sbase,
                                              const __half* A, const __half* Al,
                                              const __half* B, const __half* Bl,
                                              int k0, int tid) {
#pragma unroll
    for (int it = 0; it < 8; it++) {          // A: 256 rows x 8 16B-cols
        int idx = tid + it * 256;
        int r = idx >> 3, c = idx & 7;
        uint32_t so = sw128((uint32_t)(r * 128 + c * 16));
        size_t go = (size_t)r * KK + k0 + c * 8;
        cp16(sbase + G2<TERMS>::AHI + so, A + go);
        if (TERMS == 3) cp16(sbase + G2<TERMS>::ALO + so, Al + go);
    }
#pragma unroll
    for (int it = 0; it < 4; it++) {          // B: 128 rows x 8 16B-cols
        int idx = tid + it * 256;
        int r = idx >> 3, c = idx & 7;
        uint32_t so = sw128((uint32_t)(r * 128 + c * 16));
        size_t go = (size_t)r * KK + k0 + c * 8;
        cp16(sbase + G2<TERMS>::BHI + so, B + go);
        cp16(sbase + G2<TERMS>::BLO + so, Bl + go);
    }
    asm volatile("cp.async.commit_group;" ::: "memory");
}

template <int TERMS, int TILES, int KK, int NTOT>
__global__ void __launch_bounds__(256, 1)
gemm_hs256(const __half* __restrict__ Ahi, const __half* __restrict__ Alo,
           const __half* __restrict__ Bhi, const __half* __restrict__ Blo,
           const float* __restrict__ bias, float* __restrict__ C) {
    extern __shared__ char smc[];
    uint32_t sb = s2u(smc);
    int tid = threadIdx.x;
    int wid = tid >> 5, lane = tid & 31;
    int warp_m = wid >> 1, warp_n = wid & 1;
    int bxg = blockIdx.x, by = blockIdx.y;
    int row_in = lane & 7, grp = lane >> 3;

    constexpr int NC = KK / 64;
    constexpr int TC = TILES * NC;

    const __half* Ah = Ahi + (size_t)(by * 256) * KK;
    const __half* Al = Alo + (size_t)(by * 256) * KK;

    float acc[4][8][4] = {};
    uint32_t ahi[4][4], alo[4][4], bhi[8][2], blo[8][2];

    {
        const __half* Bh0 = Bhi + (size_t)(bxg * TILES * 128) * KK;
        const __half* Bl0 = Blo + (size_t)(bxg * TILES * 128) * KK;
        load_stage256<TERMS, KK>(sb, Ah, Al, Bh0, Bl0, 0, tid);
    }

    for (int g = 0; g < TC; g++) {
        int tile = g / NC, c = g % NC;
        asm volatile("cp.async.wait_group 0;" ::: "memory");
        __syncthreads();

        int g1 = g + 1;
        if (g1 < TC) {
            int t1 = g1 / NC, c1 = g1 % NC;
            const __half* Bh1 = Bhi + (size_t)((bxg * TILES + t1) * 128) * KK;
            const __half* Bl1 = Blo + (size_t)((bxg * TILES + t1) * 128) * KK;
            load_stage256<TERMS, KK>(sb + (g1 & 1) * G2<TERMS>::STG,
                                     Ah, Al, Bh1, Bl1, c1 * 64, tid);
        }

        uint32_t stg = sb + (g & 1) * G2<TERMS>::STG;
#pragma unroll
        for (int ks = 0; ks < 4; ks++) {
#pragma unroll
            for (int mf = 0; mf < 4; mf++) {
                int r = warp_m * 64 + mf * 16 + (grp & 1) * 8 + row_in;
                int kb = ks * 32 + (grp >> 1) * 16;
                uint32_t off = sw128((uint32_t)(r * 128 + kb));
                LDSM4(ahi[mf][0], ahi[mf][1], ahi[mf][2], ahi[mf][3],
                      stg + G2<TERMS>::AHI + off);
                if (TERMS == 3)
                    LDSM4(alo[mf][0], alo[mf][1], alo[mf][2], alo[mf][3],
                          stg + G2<TERMS>::ALO + off);
            }
#pragma unroll
            for (int p = 0; p < 4; p++) {
                int r = warp_n * 64 + p * 16 + (grp >> 1) * 8 + row_in;
                int kb = ks * 32 + (grp & 1) * 16;
                uint32_t off = sw128((uint32_t)(r * 128 + kb));
                uint32_t t0, t1, t2, t3;
                LDSM4(t0, t1, t2, t3, stg + G2<TERMS>::BHI + off);
                bhi[2 * p][0] = t0; bhi[2 * p][1] = t1;
                bhi[2 * p + 1][0] = t2; bhi[2 * p + 1][1] = t3;
                LDSM4(t0, t1, t2, t3, stg + G2<TERMS>::BLO + off);
                blo[2 * p][0] = t0; blo[2 * p][1] = t1;
                blo[2 * p + 1][0] = t2; blo[2 * p + 1][1] = t3;
            }
            // per-acc order: hibhi -> hiblo -> lobhi (unchanged)
#pragma unroll
            for (int mf = 0; mf < 4; mf++)
#pragma unroll
                for (int nf = 0; nf < 8; nf++)
                    MMA16816(acc[mf][nf], ahi[mf], bhi[nf]);
#pragma unroll
            for (int mf = 0; mf < 4; mf++)
#pragma unroll
                for (int nf = 0; nf < 8; nf++)
                    MMA16816(acc[mf][nf], ahi[mf], blo[nf]);
            if (TERMS == 3) {
#pragma unroll
                for (int mf = 0; mf < 4; mf++)
#pragma unroll
                    for (int nf = 0; nf < 8; nf++)
                        MMA16816(acc[mf][nf], alo[mf], bhi[nf]);
            }
        }

        if (c == NC - 1) {
            int col_base = (bxg * TILES + tile) * 128 + warp_n * 64 + (lane & 3) * 2;
            int row_base = by * 256 + warp_m * 64 + (lane >> 2);
#pragma unroll
            for (int mf = 0; mf < 4; mf++)
#pragma unroll
                for (int nf = 0; nf < 8; nf++) {
                    int col = col_base + nf * 8;
                    float b0 = __ldg(bias + col), b1 = __ldg(bias + col + 1);
                    int r0 = row_base + mf * 16;
                    float2 v0 = { acc[mf][nf][0] + b0, acc[mf][nf][1] + b1 };
                    float2 v1 = { acc[mf][nf][2] + b0, acc[mf][nf][3] + b1 };
                    *(float2*)(C + (size_t)r0 * NTOT + col) = v0;
                    *(float2*)(C + (size_t)(r0 + 8) * NTOT + col) = v1;
                }
#pragma unroll
            for (int mf = 0; mf < 4; mf++)
#pragma unroll
                for (int nf = 0; nf < 8; nf++)
#pragma unroll
                    for (int q = 0; q < 4; q++) acc[mf][nf][q] = 0.0f;
        }
    }
}

// ---------------------------------------------------------------------------
// Input projector, tiled (16 rows/block, W2 read once per block)
// ---------------------------------------------------------------------------
#define PR 16
__global__ void __launch_bounds__(256)
proj_kernel(const float* __restrict__ hist,
            const float* __restrict__ W1, const float* __restrict__ b1,
            const float* __restrict__ W2, const float* __restrict__ b2,
            float* __restrict__ out,
            __half* __restrict__ ohi, __half* __restrict__ olo) {
    __shared__ float hs[PR * INsz];
    __shared__ float hpT[HPsz][PR];
    int rb = blockIdx.x * PR;
    int tid = threadIdx.x;

    if (tid < PR * INsz) hs[tid] = hist[(size_t)rb * INsz + tid];
    __syncthreads();

#pragma unroll
    for (int i = 0; i < (PR * HPsz) / 256; i++) {
        int idx = tid + i * 256;
        int r = idx >> 6, cc = idx & 63;
        float a = b1[cc];
#pragma unroll
        for (int k = 0; k < INsz; k++) a += hs[r * INsz + k] * W1[k * HPsz + cc];
        hpT[cc][r] = 0.5f * a * (1.0f + erff(a * 0.70710678118654752440f));
    }
    __syncthreads();

    int c0 = tid * 2;
    float acc[PR][2];
    float bb0 = b2[c0], bb1 = b2[c0 + 1];
#pragma unroll
    for (int r = 0; r < PR; r++) { acc[r][0] = bb0; acc[r][1] = bb1; }

    for (int k = 0; k < HPsz; k++) {
        float2 w = *(const float2*)(W2 + (size_t)k * Esz + c0);
        float4 h0 = *(const float4*)&hpT[k][0];
        float4 h1 = *(const float4*)&hpT[k][4];
        float4 h2 = *(const float4*)&hpT[k][8];
        float4 h3 = *(const float4*)&hpT[k][12];
        float hk[PR] = { h0.x, h0.y, h0.z, h0.w, h1.x, h1.y, h1.z, h1.w,
                         h2.x, h2.y, h2.z, h2.w, h3.x, h3.y, h3.z, h3.w };
#pragma unroll
        for (int r = 0; r < PR; r++) {
            acc[r][0] += hk[r] * w.x;
            acc[r][1] += hk[r] * w.y;
        }
    }

#pragma unroll
    for (int r = 0; r < PR; r++) {
        size_t off = (size_t)(rb + r) * Esz + c0;
        float a0 = acc[r][0], a1 = acc[r][1];
        *(float2*)(out + off) = make_float2(a0, a1);
        __half h0 = __float2half_rn(a0), h1 = __float2half_rn(a1);
        *(__half2*)(ohi + off) = __halves2half2(h0, h1);
        *(__half2*)(olo + off) = __halves2half2(
            __float2half_rn(a0 - __half2float(h0)),
            __float2half_rn(a1 - __half2float(h1)));
    }
}

// ---------------------------------------------------------------------------
// Block reduce (order-exact)
// ---------------------------------------------------------------------------
__device__ __forceinline__ float block_reduce_sum(float v) {
    __shared__ float smr[32];
    int lane = threadIdx.x & 31, wid = threadIdx.x >> 5;
#pragma unroll
    for (int o = 16; o > 0; o >>= 1) v += __shfl_xor_sync(0xffffffffu, v, o);
    __syncthreads();
    if (lane == 0) smr[wid] = v;
    __syncthreads();
    if (wid == 0) {
        v = (lane < (int)(blockDim.x >> 5)) ? smr[lane] : 0.0f;
#pragma unroll
        for (int o = 16; o > 0; o >>= 1) v += __shfl_xor_sync(0xffffffffu, v, o);
        if (lane == 0) smr[0] = v;
    }
    __syncthreads();
    return smr[0];
}

template <int N, int NTHR>
__global__ void ln_stats(const float* __restrict__ x,
                         float* __restrict__ mean, float* __restrict__ rstd) {
    size_t row = blockIdx.x;
    const float4* p = (const float4*)(x + row * (size_t)N);
    int tid = threadIdx.x;

    float4 v = p[tid];
    float s = v.x + v.y + v.z + v.w;
    float m = block_reduce_sum(s) * (1.0f / N);

    float dx = v.x - m, dy = v.y - m, dz = v.z - m, dw = v.w - m;
    float var = block_reduce_sum(dx * dx + dy * dy + dz * dz + dw * dw) * (1.0f / N);
    float inv = 1.0f / sqrtf(var + 1e-5f);

    if (tid == 0) { mean[row] = m; rstd[row] = inv; }
}

// ---------------------------------------------------------------------------
// LIF apply (float4), LIF+residual apply
// ---------------------------------------------------------------------------
__global__ void lif_apply(const float4* __restrict__ h4,
                          const float* __restrict__ mean, const float* __restrict__ rstd,
                          const float4* __restrict__ gamma4, const float4* __restrict__ beta4,
                          uint2* __restrict__ spk4, int C4) {
    int idx = blockIdx.x * blockDim.x + threadIdx.x;
    if (idx >= Bsz * C4) return;
    int b = idx / C4, j = idx % C4;
    float4 gg = gamma4[j], bb = beta4[j];
    float v0 = 0.f, v1 = 0.f, v2 = 0.f, v3 = 0.f;
    size_t base = (size_t)b * Tsz * C4 + j;
    int rbase = b * Tsz;
#pragma unroll 4
    for (int t = 0; t < Tsz; t++) {
        float4 xi = h4[base + (size_t)t * C4];
        float m = __ldg(mean + rbase + t);
        float inv = __ldg(rstd + rbase + t);
        float n0 = (xi.x - m) * inv * gg.x + bb.x;
        float n1 = (xi.y - m) * inv * gg.y + bb.y;
        float n2 = (xi.z - m) * inv * gg.z + bb.z;
        float n3 = (xi.w - m) * inv * gg.w + bb.w;
        v0 = v0 + (n0 - v0) * 0.5f;
        v1 = v1 + (n1 - v1) * 0.5f;
        v2 = v2 + (n2 - v2) * 0.5f;
        v3 = v3 + (n3 - v3) * 0.5f;
        float s0 = 0.f, s1 = 0.f, s2 = 0.f, s3 = 0.f;
        if (v0 >= 1.0f) { s0 = 1.0f; v0 = 0.f; }
        if (v1 >= 1.0f) { s1 = 1.0f; v1 = 0.f; }
        if (v2 >= 1.0f) { s2 = 1.0f; v2 = 0.f; }
        if (v3 >= 1.0f) { s3 = 1.0f; v3 = 0.f; }
        __half2 lo2 = __halves2half2(__float2half_rn(s0), __float2half_rn(s1));
        __half2 hi2 = __halves2half2(__float2half_rn(s2), __float2half_rn(s3));
        uint2 pack = { *(uint32_t*)&lo2, *(uint32_t*)&hi2 };
        spk4[base + (size_t)t * C4] = pack;
    }
}

__global__ void lifadd_apply(const float4* __restrict__ h4,
                             const float* __restrict__ mean, const float* __restrict__ rstd,
                             const float4* __restrict__ gamma4, const float4* __restrict__ beta4,
                             float* __restrict__ x, __half* __restrict__ xhi,
                             __half* __restrict__ xlo, int C4) {
    int idx = blockIdx.x * blockDim.x + threadIdx.x;
    if (idx >= Bsz * C4) return;
    int b = idx / C4, j = idx % C4;
    float4 gg = gamma4[j], bb = beta4[j];
    float v0 = 0.f, v1 = 0.f, v2 = 0.f, v3 = 0.f;
    size_t base = (size_t)b * Tsz * C4 + j;
    int rbase = b * Tsz;
    int C = C4 * 4;
#pragma unroll 4
    for (int t = 0; t < Tsz; t++) {
        float4 xi = h4[base + (size_t)t * C4];
        float m = __ldg(mean + rbase + t);
        float inv = __ldg(rstd + rbase + t);
        float n0 = (xi.x - m) * inv * gg.x + bb.x;
        float n1 = (xi.y - m) * inv * gg.y + bb.y;
        float n2 = (xi.z - m) * inv * gg.z + bb.z;
        float n3 = (xi.w - m) * inv * gg.w + bb.w;
        v0 = v0 + (n0 - v0) * 0.5f;
        v1 = v1 + (n1 - v1) * 0.5f;
        v2 = v2 + (n2 - v2) * 0.5f;
        v3 = v3 + (n3 - v3) * 0.5f;
        size_t o = (size_t)b * Tsz * C + (size_t)t * C + j * 4;
#pragma unroll
        for (int cc = 0; cc < 4; cc++) {
            float* vp = (cc == 0) ? &v0 : (cc == 1) ? &v1 : (cc == 2) ? &v2 : &v3;
            if (*vp >= 1.0f) {
                *vp = 0.f;
                float xv = x[o + cc] + 1.0f;
                x[o + cc] = xv;
                __half hh = __float2half_rn(xv);
                xhi[o + cc] = hh;
                xlo[o + cc] = __float2half_rn(xv - __half2float(hh));
            }
        }
    }
}

// Extract last timestep
__global__ void last_kernel(const float* __restrict__ x, float* __restrict__ out) {
    int i = blockIdx.x * blockDim.x + threadIdx.x;
    if (i < Bsz * Esz) {
        int b = i / Esz, e = i % Esz;
        out[i] = x[((size_t)b * Tsz + (Tsz - 1)) * Esz + e];
    }
}

// ---------------------------------------------------------------------------
extern "C" void kernel_launch(void* const* d_in, const int* in_sizes, int n_in,
                              void* d_out, int out_size) {
    const float* hist  = (const float*)d_in[0];
    const float* pW1   = (const float*)d_in[1];
    const float* pb1   = (const float*)d_in[2];
    const float* pW2   = (const float*)d_in[3];
    const float* pb2   = (const float*)d_in[4];
    const float* fc1_w = (const float*)d_in[5];
    const float* fc1_b = (const float*)d_in[6];
    const float* ln1_g = (const float*)d_in[7];
    const float* ln1_b = (const float*)d_in[8];
    const float* fc2_w = (const float*)d_in[9];
    const float* fc2_b = (const float*)d_in[10];
    const float* ln2_g = (const float*)d_in[11];
    const float* ln2_b = (const float*)d_in[12];

    float *x, *h1, *h2, *mean, *rstd;
    __half *xhi, *xlo, *spk, *w1hi, *w1lo, *w2hi, *w2lo;
    cudaGetSymbolAddress((void**)&x,    g_x);
    cudaGetSymbolAddress((void**)&h1,   g_h1);
    cudaGetSymbolAddress((void**)&h2,   g_h2);
    cudaGetSymbolAddress((void**)&mean, g_mean);
    cudaGetSymbolAddress((void**)&rstd, g_rstd);
    cudaGetSymbolAddress((void**)&xhi,  g_xhi);
    cudaGetSymbolAddress((void**)&xlo,  g_xlo);
    cudaGetSymbolAddress((void**)&spk,  g_spk);
    cudaGetSymbolAddress((void**)&w1hi, g_w1hi);
    cudaGetSymbolAddress((void**)&w1lo, g_w1lo);
    cudaGetSymbolAddress((void**)&w2hi, g_w2hi);
    cudaGetSymbolAddress((void**)&w2lo, g_w2lo);

    auto* gk1 = gemm_hs256<3, 2, Esz, Hsz>;   // GEMM1: K=512, N=1024, 2 N-tiles/CTA
    auto* gk2 = gemm_hs256<2, 1, Hsz, Esz>;   // GEMM2: K=1024, N=512, 1 N-tile/CTA
    cudaFuncSetAttribute(gk1, cudaFuncAttributeMaxDynamicSharedMemorySize, G2<3>::TOT);
    cudaFuncSetAttribute(gk2, cudaFuncAttributeMaxDynamicSharedMemorySize, G2<2>::TOT);

    split_w<<<dim3((Esz * Hsz + 255) / 256, Dsz), 256>>>(fc1_w, w1hi, w1lo, Esz, Hsz);
    split_w<<<dim3((Hsz * Esz + 255) / 256, Dsz), 256>>>(fc2_w, w2hi, w2lo, Hsz, Esz);

    proj_kernel<<<ROWS / PR, 256>>>(hist, pW1, pb1, pW2, pb2, x, xhi, xlo);

    for (int d = 0; d < Dsz; d++) {
        size_t o1 = (size_t)d * Hsz * Esz;
        size_t o2 = (size_t)d * Esz * Hsz;

        gk1<<<dim3(Hsz / 128 / 2, ROWS / 256), 256, G2<3>::TOT>>>(
            xhi, xlo, w1hi + o1, w1lo + o1, fc1_b + d * Hsz, h1);
        ln_stats<Hsz, 256><<<ROWS, 256>>>(h1, mean, rstd);
        lif_apply<<<(Bsz * (Hsz / 4) + 255) / 256, 256>>>(
            (const float4*)h1, mean, rstd, (const float4*)(ln1_g + d * Hsz),
            (const float4*)(ln1_b + d * Hsz), (uint2*)spk, Hsz / 4);

        gk2<<<dim3(Esz / 128, ROWS / 256), 256, G2<2>::TOT>>>(
            spk, spk, w2hi + o2, w2lo + o2, fc2_b + d * Esz, h2);
        ln_stats<Esz, 128><<<ROWS, 128>>>(h2, mean, rstd);
        lifadd_apply<<<(Bsz * (Esz / 4) + 255) / 256, 256>>>(
            (const float4*)h2, mean, rstd, (const float4*)(ln2_g + d * Esz),
            (const float4*)(ln2_b + d * Esz), x, xhi, xlo, Esz / 4);
    }

    last_kernel<<<(Bsz * Esz + 255) / 256, 256>>>(x, (float*)d_out);
}

// round 10
// speedup vs baseline: 1.1255x; 1.0629x over previous
#include <cuda_runtime.h>
#include <cuda_fp16.h>
#include <math.h>
#include <stdint.h>

// Problem dims
#define Bsz  256
#define Tsz  256
#define INsz 4
#define HPsz 64
#define Esz  512
#define Hsz  1024
#define Dsz  4
#define ROWS (Bsz * Tsz)   // 65536

// ---------------------------------------------------------------------------
// Scratch (device globals; no allocation allowed)
// ---------------------------------------------------------------------------
__device__ float  g_x  [(size_t)ROWS * Esz];
__device__ __half g_xhi[(size_t)ROWS * Esz];
__device__ __half g_xlo[(size_t)ROWS * Esz];
__device__ float  g_h1 [(size_t)ROWS * Hsz];
__device__ __half g_spk[(size_t)ROWS * Hsz];
__device__ float  g_h2 [(size_t)ROWS * Esz];
__device__ float  g_mean[ROWS];
__device__ float  g_rstd[ROWS];
__device__ float  g_psum[(size_t)ROWS * 8];    // per-tile partial sums
__device__ float  g_psq [(size_t)ROWS * 8];    // per-tile partial sum-of-squares
__device__ __half g_w1hi[(size_t)Dsz * Hsz * Esz];
__device__ __half g_w1lo[(size_t)Dsz * Hsz * Esz];
__device__ __half g_w2hi[(size_t)Dsz * Esz * Hsz];
__device__ __half g_w2lo[(size_t)Dsz * Esz * Hsz];

// ---------------------------------------------------------------------------
// Helpers
// ---------------------------------------------------------------------------
__device__ __forceinline__ uint32_t sw128(uint32_t b) { return b ^ ((b >> 3) & 0x70); }

__device__ __forceinline__ uint32_t s2u(const void* p) {
    uint32_t a;
    asm("{ .reg .u64 t; cvta.to.shared.u64 t, %1; cvt.u32.u64 %0, t; }" : "=r"(a) : "l"(p));
    return a;
}

__device__ __forceinline__ void cp16(uint32_t saddr, const void* g) {
    asm volatile("cp.async.cg.shared.global [%0], [%1], 16;" :: "r"(saddr), "l"(g));
}

#define LDSM4(r0, r1, r2, r3, addr)                                           \
    asm volatile("ldmatrix.sync.aligned.m8n8.x4.shared.b16 {%0,%1,%2,%3}, [%4];" \
                 : "=r"(r0), "=r"(r1), "=r"(r2), "=r"(r3) : "r"(addr))

#define MMA16816(d, a, b)                                                     \
    asm volatile(                                                             \
        "mma.sync.aligned.m16n8k16.row.col.f32.f16.f16.f32 "                  \
        "{%0,%1,%2,%3},{%4,%5,%6,%7},{%8,%9},{%0,%1,%2,%3};"                  \
        : "+f"((d)[0]), "+f"((d)[1]), "+f"((d)[2]), "+f"((d)[3])              \
        : "r"((a)[0]), "r"((a)[1]), "r"((a)[2]), "r"((a)[3]),                 \
          "r"((b)[0]), "r"((b)[1]))

// ---------------------------------------------------------------------------
// Split+transpose weights
// ---------------------------------------------------------------------------
__global__ void split_w(const float* __restrict__ W, __half* __restrict__ hi,
                        __half* __restrict__ lo, int K, int N) {
    int idx = blockIdx.x * blockDim.x + threadIdx.x;
    if (idx >= K * N) return;
    size_t lofs = (size_t)blockIdx.y * K * N;
    int k = idx / N, n = idx % N;
    float w = W[lofs + idx];
    __half h = __float2half_rn(w);
    hi[lofs + (size_t)n * K + k] = h;
    lo[lofs + (size_t)n * K + k] = __float2half_rn(w - __half2float(h));
}

// ---------------------------------------------------------------------------
// GEMM: C = Ahi@Bhi^T + Ahi@Blo^T (+ Alo@Bhi^T) + bias; epilogue also emits
// per-tile LN partial (sum, sumsq) per row via fixed-order smem reduction.
// CTA tile 256x128, warp tile 64x64 (8 warps 4x2), BK=64, 2-stage cp.async.
// ---------------------------------------------------------------------------
template <int TERMS> struct G2 {
    static constexpr int AHI = 0;
    static constexpr int ALO = 32768;
    static constexpr int BHI = (TERMS == 3) ? 65536 : 32768;
    static constexpr int BLO = BHI + 16384;
    static constexpr int STG = BLO + 16384;      // 96 KB / 64 KB
    static constexpr int STATS = 2 * STG;        // stats smem region
    static constexpr int TOT = STATS + 16384;    // +16 KB (256 rows x 8 x 2 floats)
};

template <int TERMS, int KK>
__device__ __forceinline__ void load_stage256(uint32_t sbase,
                                              const __half* A, const __half* Al,
                                              const __half* B, const __half* Bl,
                                              int k0, int tid) {
#pragma unroll
    for (int it = 0; it < 8; it++) {          // A: 256 rows x 8 16B-cols
        int idx = tid + it * 256;
        int r = idx >> 3, c = idx & 7;
        uint32_t so = sw128((uint32_t)(r * 128 + c * 16));
        size_t go = (size_t)r * KK + k0 + c * 8;
        cp16(sbase + G2<TERMS>::AHI + so, A + go);
        if (TERMS == 3) cp16(sbase + G2<TERMS>::ALO + so, Al + go);
    }
#pragma unroll
    for (int it = 0; it < 4; it++) {          // B: 128 rows x 8 16B-cols
        int idx = tid + it * 256;
        int r = idx >> 3, c = idx & 7;
        uint32_t so = sw128((uint32_t)(r * 128 + c * 16));
        size_t go = (size_t)r * KK + k0 + c * 8;
        cp16(sbase + G2<TERMS>::BHI + so, B + go);
        cp16(sbase + G2<TERMS>::BLO + so, Bl + go);
    }
    asm volatile("cp.async.commit_group;" ::: "memory");
}

template <int TERMS, int TILES, int KK, int NTOT>
__global__ void __launch_bounds__(256, 1)
gemm_hs256(const __half* __restrict__ Ahi, const __half* __restrict__ Alo,
           const __half* __restrict__ Bhi, const __half* __restrict__ Blo,
           const float* __restrict__ bias, float* __restrict__ C,
           float* __restrict__ psum, float* __restrict__ psq) {
    extern __shared__ char smc[];
    uint32_t sb = s2u(smc);
    float* ssum = (float*)(smc + G2<TERMS>::STATS);          // [256][8]
    float* ssq  = (float*)(smc + G2<TERMS>::STATS + 8192);   // [256][8]
    int tid = threadIdx.x;
    int wid = tid >> 5, lane = tid & 31;
    int warp_m = wid >> 1, warp_n = wid & 1;
    int bxg = blockIdx.x, by = blockIdx.y;
    int row_in = lane & 7, grp = lane >> 3;

    constexpr int NC = KK / 64;
    constexpr int TC = TILES * NC;
    constexpr int NPART = NTOT / 128;

    const __half* Ah = Ahi + (size_t)(by * 256) * KK;
    const __half* Al = Alo + (size_t)(by * 256) * KK;

    float acc[4][8][4] = {};
    uint32_t ahi[4][4], alo[4][4], bhi[8][2], blo[8][2];

    {
        const __half* Bh0 = Bhi + (size_t)(bxg * TILES * 128) * KK;
        const __half* Bl0 = Blo + (size_t)(bxg * TILES * 128) * KK;
        load_stage256<TERMS, KK>(sb, Ah, Al, Bh0, Bl0, 0, tid);
    }

    for (int g = 0; g < TC; g++) {
        int tile = g / NC, c = g % NC;
        asm volatile("cp.async.wait_group 0;" ::: "memory");
        __syncthreads();

        int g1 = g + 1;
        if (g1 < TC) {
            int t1 = g1 / NC, c1 = g1 % NC;
            const __half* Bh1 = Bhi + (size_t)((bxg * TILES + t1) * 128) * KK;
            const __half* Bl1 = Blo + (size_t)((bxg * TILES + t1) * 128) * KK;
            load_stage256<TERMS, KK>(sb + (g1 & 1) * G2<TERMS>::STG,
                                     Ah, Al, Bh1, Bl1, c1 * 64, tid);
        }

        uint32_t stg = sb + (g & 1) * G2<TERMS>::STG;
#pragma unroll
        for (int ks = 0; ks < 4; ks++) {
#pragma unroll
            for (int mf = 0; mf < 4; mf++) {
                int r = warp_m * 64 + mf * 16 + (grp & 1) * 8 + row_in;
                int kb = ks * 32 + (grp >> 1) * 16;
                uint32_t off = sw128((uint32_t)(r * 128 + kb));
                LDSM4(ahi[mf][0], ahi[mf][1], ahi[mf][2], ahi[mf][3],
                      stg + G2<TERMS>::AHI + off);
                if (TERMS == 3)
                    LDSM4(alo[mf][0], alo[mf][1], alo[mf][2], alo[mf][3],
                          stg + G2<TERMS>::ALO + off);
            }
#pragma unroll
            for (int p = 0; p < 4; p++) {
                int r = warp_n * 64 + p * 16 + (grp >> 1) * 8 + row_in;
                int kb = ks * 32 + (grp & 1) * 16;
                uint32_t off = sw128((uint32_t)(r * 128 + kb));
                uint32_t t0, t1, t2, t3;
                LDSM4(t0, t1, t2, t3, stg + G2<TERMS>::BHI + off);
                bhi[2 * p][0] = t0; bhi[2 * p][1] = t1;
                bhi[2 * p + 1][0] = t2; bhi[2 * p + 1][1] = t3;
                LDSM4(t0, t1, t2, t3, stg + G2<TERMS>::BLO + off);
                blo[2 * p][0] = t0; blo[2 * p][1] = t1;
                blo[2 * p + 1][0] = t2; blo[2 * p + 1][1] = t3;
            }
            // per-acc order: hibhi -> hiblo -> lobhi (unchanged)
#pragma unroll
            for (int mf = 0; mf < 4; mf++)
#pragma unroll
                for (int nf = 0; nf < 8; nf++)
                    MMA16816(acc[mf][nf], ahi[mf], bhi[nf]);
#pragma unroll
            for (int mf = 0; mf < 4; mf++)
#pragma unroll
                for (int nf = 0; nf < 8; nf++)
                    MMA16816(acc[mf][nf], ahi[mf], blo[nf]);
            if (TERMS == 3) {
#pragma unroll
                for (int mf = 0; mf < 4; mf++)
#pragma unroll
                    for (int nf = 0; nf < 8; nf++)
                        MMA16816(acc[mf][nf], alo[mf], bhi[nf]);
            }
        }

        if (c == NC - 1) {
            // ---- epilogue: bias + store + LN partial stats ----
            int col_base = (bxg * TILES + tile) * 128 + warp_n * 64 + (lane & 3) * 2;
            int row_base = by * 256 + warp_m * 64 + (lane >> 2);
            int contrib = warp_n * 4 + (lane & 3);   // 0..7 per row
#pragma unroll
            for (int mf = 0; mf < 4; mf++) {
                float lsA = 0.f, lqA = 0.f, lsB = 0.f, lqB = 0.f;
#pragma unroll
                for (int nf = 0; nf < 8; nf++) {
                    int col = col_base + nf * 8;
                    float b0 = __ldg(bias + col), b1 = __ldg(bias + col + 1);
                    int r0 = row_base + mf * 16;
                    float2 v0 = { acc[mf][nf][0] + b0, acc[mf][nf][1] + b1 };
                    float2 v1 = { acc[mf][nf][2] + b0, acc[mf][nf][3] + b1 };
                    *(float2*)(C + (size_t)r0 * NTOT + col) = v0;
                    *(float2*)(C + (size_t)(r0 + 8) * NTOT + col) = v1;
                    lsA += v0.x + v0.y; lqA += v0.x * v0.x + v0.y * v0.y;
                    lsB += v1.x + v1.y; lqB += v1.x * v1.x + v1.y * v1.y;
                }
                int rA = warp_m * 64 + mf * 16 + (lane >> 2);   // 0..255 in CTA
                ssum[rA * 8 + contrib] = lsA;
                ssq [rA * 8 + contrib] = lqA;
                ssum[(rA + 8) * 8 + contrib] = lsB;
                ssq [(rA + 8) * 8 + contrib] = lqB;
#pragma unroll
                for (int nf = 0; nf < 8; nf++)
#pragma unroll
                    for (int q = 0; q < 4; q++) acc[mf][nf][q] = 0.0f;
            }
            __syncthreads();
            {
                float s = 0.f, q = 0.f;
#pragma unroll
                for (int p = 0; p < 8; p++) { s += ssum[tid * 8 + p]; q += ssq[tid * 8 + p]; }
                int tcol = bxg * TILES + tile;
                size_t row = (size_t)(by * 256 + tid);
                psum[row * NPART + tcol] = s;
                psq [row * NPART + tcol] = q;
            }
            __syncthreads();
        }
    }
}

// ---------------------------------------------------------------------------
// Finish LN stats: fixed-order reduce of per-tile partials.
// var = E[x^2] - m^2 (guarded), rstd = 1/sqrt(var + eps)
// ---------------------------------------------------------------------------
template <int NPART, int N>
__global__ void stats_finish(const float* __restrict__ psum, const float* __restrict__ psq,
                             float* __restrict__ mean, float* __restrict__ rstd) {
    int row = blockIdx.x * blockDim.x + threadIdx.x;
    if (row >= ROWS) return;
    float s = 0.f, q = 0.f;
#pragma unroll
    for (int p = 0; p < NPART; p++) {
        s += psum[(size_t)row * NPART + p];
        q += psq [(size_t)row * NPART + p];
    }
    float m = s * (1.0f / N);
    float var = fmaxf(q * (1.0f / N) - m * m, 0.0f);
    mean[row] = m;
    rstd[row] = 1.0f / sqrtf(var + 1e-5f);
}

// ---------------------------------------------------------------------------
// Input projector, tiled (16 rows/block, W2 read once per block)
// ---------------------------------------------------------------------------
#define PR 16
__global__ void __launch_bounds__(256)
proj_kernel(const float* __restrict__ hist,
            const float* __restrict__ W1, const float* __restrict__ b1,
            const float* __restrict__ W2, const float* __restrict__ b2,
            float* __restrict__ out,
            __half* __restrict__ ohi, __half* __restrict__ olo) {
    __shared__ float hs[PR * INsz];
    __shared__ float hpT[HPsz][PR];
    int rb = blockIdx.x * PR;
    int tid = threadIdx.x;

    if (tid < PR * INsz) hs[tid] = hist[(size_t)rb * INsz + tid];
    __syncthreads();

#pragma unroll
    for (int i = 0; i < (PR * HPsz) / 256; i++) {
        int idx = tid + i * 256;
        int r = idx >> 6, cc = idx & 63;
        float a = b1[cc];
#pragma unroll
        for (int k = 0; k < INsz; k++) a += hs[r * INsz + k] * W1[k * HPsz + cc];
        hpT[cc][r] = 0.5f * a * (1.0f + erff(a * 0.70710678118654752440f));
    }
    __syncthreads();

    int c0 = tid * 2;
    float acc[PR][2];
    float bb0 = b2[c0], bb1 = b2[c0 + 1];
#pragma unroll
    for (int r = 0; r < PR; r++) { acc[r][0] = bb0; acc[r][1] = bb1; }

    for (int k = 0; k < HPsz; k++) {
        float2 w = *(const float2*)(W2 + (size_t)k * Esz + c0);
        float4 h0 = *(const float4*)&hpT[k][0];
        float4 h1 = *(const float4*)&hpT[k][4];
        float4 h2 = *(const float4*)&hpT[k][8];
        float4 h3 = *(const float4*)&hpT[k][12];
        float hk[PR] = { h0.x, h0.y, h0.z, h0.w, h1.x, h1.y, h1.z, h1.w,
                         h2.x, h2.y, h2.z, h2.w, h3.x, h3.y, h3.z, h3.w };
#pragma unroll
        for (int r = 0; r < PR; r++) {
            acc[r][0] += hk[r] * w.x;
            acc[r][1] += hk[r] * w.y;
        }
    }

#pragma unroll
    for (int r = 0; r < PR; r++) {
        size_t off = (size_t)(rb + r) * Esz + c0;
        float a0 = acc[r][0], a1 = acc[r][1];
        *(float2*)(out + off) = make_float2(a0, a1);
        __half h0 = __float2half_rn(a0), h1 = __float2half_rn(a1);
        *(__half2*)(ohi + off) = __halves2half2(h0, h1);
        *(__half2*)(olo + off) = __halves2half2(
            __float2half_rn(a0 - __half2float(h0)),
            __float2half_rn(a1 - __half2float(h1)));
    }
}

// ---------------------------------------------------------------------------
// LIF apply (float4), LIF+residual apply
// ---------------------------------------------------------------------------
__global__ void lif_apply(const float4* __restrict__ h4,
                          const float* __restrict__ mean, const float* __restrict__ rstd,
                          const float4* __restrict__ gamma4, const float4* __restrict__ beta4,
                          uint2* __restrict__ spk4, int C4) {
    int idx = blockIdx.x * blockDim.x + threadIdx.x;
    if (idx >= Bsz * C4) return;
    int b = idx / C4, j = idx % C4;
    float4 gg = gamma4[j], bb = beta4[j];
    float v0 = 0.f, v1 = 0.f, v2 = 0.f, v3 = 0.f;
    size_t base = (size_t)b * Tsz * C4 + j;
    int rbase = b * Tsz;
#pragma unroll 4
    for (int t = 0; t < Tsz; t++) {
        float4 xi = h4[base + (size_t)t * C4];
        float m = __ldg(mean + rbase + t);
        float inv = __ldg(rstd + rbase + t);
        float n0 = (xi.x - m) * inv * gg.x + bb.x;
        float n1 = (xi.y - m) * inv * gg.y + bb.y;
        float n2 = (xi.z - m) * inv * gg.z + bb.z;
        float n3 = (xi.w - m) * inv * gg.w + bb.w;
        v0 = v0 + (n0 - v0) * 0.5f;
        v1 = v1 + (n1 - v1) * 0.5f;
        v2 = v2 + (n2 - v2) * 0.5f;
        v3 = v3 + (n3 - v3) * 0.5f;
        float s0 = 0.f, s1 = 0.f, s2 = 0.f, s3 = 0.f;
        if (v0 >= 1.0f) { s0 = 1.0f; v0 = 0.f; }
        if (v1 >= 1.0f) { s1 = 1.0f; v1 = 0.f; }
        if (v2 >= 1.0f) { s2 = 1.0f; v2 = 0.f; }
        if (v3 >= 1.0f) { s3 = 1.0f; v3 = 0.f; }
        __half2 lo2 = __halves2half2(__float2half_rn(s0), __float2half_rn(s1));
        __half2 hi2 = __halves2half2(__float2half_rn(s2), __float2half_rn(s3));
        uint2 pack = { *(uint32_t*)&lo2, *(uint32_t*)&hi2 };
        spk4[base + (size_t)t * C4] = pack;
    }
}

__global__ void lifadd_apply(const float4* __restrict__ h4,
                             const float* __restrict__ mean, const float* __restrict__ rstd,
                             const float4* __restrict__ gamma4, const float4* __restrict__ beta4,
                             float* __restrict__ x, __half* __restrict__ xhi,
                             __half* __restrict__ xlo, int C4) {
    int idx = blockIdx.x * blockDim.x + threadIdx.x;
    if (idx >= Bsz * C4) return;
    int b = idx / C4, j = idx % C4;
    float4 gg = gamma4[j], bb = beta4[j];
    float v0 = 0.f, v1 = 0.f, v2 = 0.f, v3 = 0.f;
    size_t base = (size_t)b * Tsz * C4 + j;
    int rbase = b * Tsz;
    int C = C4 * 4;
#pragma unroll 4
    for (int t = 0; t < Tsz; t++) {
        float4 xi = h4[base + (size_t)t * C4];
        float m = __ldg(mean + rbase + t);
        float inv = __ldg(rstd + rbase + t);
        float n0 = (xi.x - m) * inv * gg.x + bb.x;
        float n1 = (xi.y - m) * inv * gg.y + bb.y;
        float n2 = (xi.z - m) * inv * gg.z + bb.z;
        float n3 = (xi.w - m) * inv * gg.w + bb.w;
        v0 = v0 + (n0 - v0) * 0.5f;
        v1 = v1 + (n1 - v1) * 0.5f;
        v2 = v2 + (n2 - v2) * 0.5f;
        v3 = v3 + (n3 - v3) * 0.5f;
        size_t o = (size_t)b * Tsz * C + (size_t)t * C + j * 4;
#pragma unroll
        for (int cc = 0; cc < 4; cc++) {
            float* vp = (cc == 0) ? &v0 : (cc == 1) ? &v1 : (cc == 2) ? &v2 : &v3;
            if (*vp >= 1.0f) {
                *vp = 0.f;
                float xv = x[o + cc] + 1.0f;
                x[o + cc] = xv;
                __half hh = __float2half_rn(xv);
                xhi[o + cc] = hh;
                xlo[o + cc] = __float2half_rn(xv - __half2float(hh));
            }
        }
    }
}

// Extract last timestep
__global__ void last_kernel(const float* __restrict__ x, float* __restrict__ out) {
    int i = blockIdx.x * blockDim.x + threadIdx.x;
    if (i < Bsz * Esz) {
        int b = i / Esz, e = i % Esz;
        out[i] = x[((size_t)b * Tsz + (Tsz - 1)) * Esz + e];
    }
}

// ---------------------------------------------------------------------------
extern "C" void kernel_launch(void* const* d_in, const int* in_sizes, int n_in,
                              void* d_out, int out_size) {
    const float* hist  = (const float*)d_in[0];
    const float* pW1   = (const float*)d_in[1];
    const float* pb1   = (const float*)d_in[2];
    const float* pW2   = (const float*)d_in[3];
    const float* pb2   = (const float*)d_in[4];
    const float* fc1_w = (const float*)d_in[5];
    const float* fc1_b = (const float*)d_in[6];
    const float* ln1_g = (const float*)d_in[7];
    const float* ln1_b = (const float*)d_in[8];
    const float* fc2_w = (const float*)d_in[9];
    const float* fc2_b = (const float*)d_in[10];
    const float* ln2_g = (const float*)d_in[11];
    const float* ln2_b = (const float*)d_in[12];

    float *x, *h1, *h2, *mean, *rstd, *psum, *psq;
    __half *xhi, *xlo, *spk, *w1hi, *w1lo, *w2hi, *w2lo;
    cudaGetSymbolAddress((void**)&x,    g_x);
    cudaGetSymbolAddress((void**)&h1,   g_h1);
    cudaGetSymbolAddress((void**)&h2,   g_h2);
    cudaGetSymbolAddress((void**)&mean, g_mean);
    cudaGetSymbolAddress((void**)&rstd, g_rstd);
    cudaGetSymbolAddress((void**)&psum, g_psum);
    cudaGetSymbolAddress((void**)&psq,  g_psq);
    cudaGetSymbolAddress((void**)&xhi,  g_xhi);
    cudaGetSymbolAddress((void**)&xlo,  g_xlo);
    cudaGetSymbolAddress((void**)&spk,  g_spk);
    cudaGetSymbolAddress((void**)&w1hi, g_w1hi);
    cudaGetSymbolAddress((void**)&w1lo, g_w1lo);
    cudaGetSymbolAddress((void**)&w2hi, g_w2hi);
    cudaGetSymbolAddress((void**)&w2lo, g_w2lo);

    auto* gk1 = gemm_hs256<3, 2, Esz, Hsz>;   // GEMM1: K=512, N=1024, 2 N-tiles/CTA
    auto* gk2 = gemm_hs256<2, 1, Hsz, Esz>;   // GEMM2: K=1024, N=512, 1 N-tile/CTA
    cudaFuncSetAttribute(gk1, cudaFuncAttributeMaxDynamicSharedMemorySize, G2<3>::TOT);
    cudaFuncSetAttribute(gk2, cudaFuncAttributeMaxDynamicSharedMemorySize, G2<2>::TOT);

    split_w<<<dim3((Esz * Hsz + 255) / 256, Dsz), 256>>>(fc1_w, w1hi, w1lo, Esz, Hsz);
    split_w<<<dim3((Hsz * Esz + 255) / 256, Dsz), 256>>>(fc2_w, w2hi, w2lo, Hsz, Esz);

    proj_kernel<<<ROWS / PR, 256>>>(hist, pW1, pb1, pW2, pb2, x, xhi, xlo);

    for (int d = 0; d < Dsz; d++) {
        size_t o1 = (size_t)d * Hsz * Esz;
        size_t o2 = (size_t)d * Esz * Hsz;

        gk1<<<dim3(Hsz / 128 / 2, ROWS / 256), 256, G2<3>::TOT>>>(
            xhi, xlo, w1hi + o1, w1lo + o1, fc1_b + d * Hsz, h1, psum, psq);
        stats_finish<Hsz / 128, Hsz><<<ROWS / 256, 256>>>(psum, psq, mean, rstd);
        lif_apply<<<(Bsz * (Hsz / 4) + 255) / 256, 256>>>(
            (const float4*)h1, mean, rstd, (const float4*)(ln1_g + d * Hsz),
            (const float4*)(ln1_b + d * Hsz), (uint2*)spk, Hsz / 4);

        gk2<<<dim3(Esz / 128, ROWS / 256), 256, G2<2>::TOT>>>(
            spk, spk, w2hi + o2, w2lo + o2, fc2_b + d * Esz, h2, psum, psq);
        stats_finish<Esz / 128, Esz><<<ROWS / 256, 256>>>(psum, psq, mean, rstd);
        lifadd_apply<<<(Bsz * (Esz / 4) + 255) / 256, 256>>>(
            (const float4*)h2, mean, rstd, (const float4*)(ln2_g + d * Esz),
            (const float4*)(ln2_b + d * Esz), x, xhi, xlo, Esz / 4);
    }

    last_kernel<<<(Bsz * Esz + 255) / 256, 256>>>(x, (float*)d_out);
}